// round 17
// baseline (speedup 1.0000x reference)
#include <cuda_runtime.h>

// Problem constants: B=8, T=4096, C=32 (embedding), D=64 (head)
#define B_  8
#define T_  4096
#define C_  32
#define D_  64
#define NQT128 32            // 128-wide query tiles per batch
#define NCHUNK 16            // k-chunks per query tile (each <=4 k-passes of 64)
#define CHUNKP 4             // k-passes per chunk

typedef unsigned long long ull;
typedef unsigned int uint;

// ---- attn kernel smem layout (floats) ----
// ys strides 136 (=8 mod 32), xT stride 72 (=8 mod 32): conflict-free mma
// fragment loads (bank = 8*c + pos covers all 32 banks).
#define YSP    136
#define XTP    72
#define YSH_OFF 0                      // ys_hi[32][136] = 4352
#define YSL_OFF 4352                   // ys_lo[32][136] = 4352
#define XT_STR (32 * XTP)              // one xT buffer  = 2304
#define XT_OFF 8704                    // xT[2][32][72]  = 4608
#define XN_STR (64 * 36)               // one xN buffer  = 2304
#define XN_OFF (XT_OFF + 2 * XT_STR)   // xN[2][64][36]  = 4608
#define PS_OFF (XN_OFF + 2 * XN_STR)   // Ps[128][68]    = 8704
#define SM_FLOATS (PS_OFF + 128 * 68)  // 26624 floats = 106496 B -> 2 CTAs/SM

// y = x * (Wq Wk^T)  [B*T, 32]
__device__ float g_y[B_ * T_ * C_];
// split-K partials: slot = ((b*32+qt)*16 + chunk)
__device__ float g_partZ[B_ * NQT128 * NCHUNK * 128 * 32];
__device__ float g_partL[B_ * NQT128 * NCHUNK * 128];

// ---------------------------------------------------------------------------
// packed f32x2 / tf32 helpers
// ---------------------------------------------------------------------------
__device__ __forceinline__ ull pack2(float a, float b) {
    ull r; asm("mov.b64 %0, {%1, %2};" : "=l"(r) : "f"(a), "f"(b)); return r;
}
__device__ __forceinline__ float2 unpack2(ull v) {
    float2 r; asm("mov.b64 {%0, %1}, %2;" : "=f"(r.x), "=f"(r.y) : "l"(v)); return r;
}
__device__ __forceinline__ void fma2(ull& d, ull a, ull b) {
    asm("fma.rn.f32x2 %0, %1, %2, %0;" : "+l"(d) : "l"(a), "l"(b));
}
__device__ __forceinline__ uint f2tf32(float f) {
    uint r; asm("cvt.rna.tf32.f32 %0, %1;" : "=r"(r) : "f"(f)); return r;
}
__device__ __forceinline__ void mma_tf32(float* d, const uint* a, uint b0, uint b1) {
    asm("mma.sync.aligned.m16n8k8.row.col.f32.tf32.tf32.f32 "
        "{%0,%1,%2,%3}, {%4,%5,%6,%7}, {%8,%9}, {%0,%1,%2,%3};"
        : "+f"(d[0]), "+f"(d[1]), "+f"(d[2]), "+f"(d[3])
        : "r"(a[0]), "r"(a[1]), "r"(a[2]), "r"(a[3]), "r"(b0), "r"(b1));
}

// ---------------------------------------------------------------------------
// Kernel 0: y = x * (Wq Wk^T).  One CTA = 128 rows (R13/R16-proven).
// ---------------------------------------------------------------------------
__global__ __launch_bounds__(256) void y_kernel(
    const float* __restrict__ x, const float* __restrict__ Wk,
    const float* __restrict__ Wq)
{
    __shared__ float Wqt[64 * 33];
    __shared__ float Wkt[64 * 33];
    __shared__ float Ms[32 * 34];
    __shared__ float xs[128 * 36];
    __shared__ float ysb[128 * 36];

    const int tid  = threadIdx.x;
    const int row0 = blockIdx.x * 128;

    {
        const float4* wq = (const float4*)Wq;
        const float4* wk = (const float4*)Wk;
        #pragma unroll
        for (int it = 0; it < 2; it++) {
            int lin = tid + it * 256;
            int r = lin >> 4, d0 = (lin & 15) * 4;
            float4 q4 = wq[lin];
            Wqt[(d0 + 0) * 33 + r] = q4.x;
            Wqt[(d0 + 1) * 33 + r] = q4.y;
            Wqt[(d0 + 2) * 33 + r] = q4.z;
            Wqt[(d0 + 3) * 33 + r] = q4.w;
            float4 k4 = wk[lin];
            Wkt[(d0 + 0) * 33 + r] = k4.x;
            Wkt[(d0 + 1) * 33 + r] = k4.y;
            Wkt[(d0 + 2) * 33 + r] = k4.z;
            Wkt[(d0 + 3) * 33 + r] = k4.w;
        }
        const float4* xg = (const float4*)(x + row0 * C_);
        #pragma unroll
        for (int it = 0; it < 4; it++) {
            int lin = tid + it * 256;
            int r = lin >> 3, c4 = lin & 7;
            *(float4*)&xs[r * 36 + c4 * 4] = xg[lin];
        }
    }
    __syncthreads();

    {
        const int i  = tid >> 3;
        const int j0 = (tid & 7) * 4;
        float a0 = 0.f, a1 = 0.f, a2 = 0.f, a3 = 0.f;
        #pragma unroll 16
        for (int d = 0; d < D_; d++) {
            float qv = Wqt[d * 33 + i];
            const float* wkr = &Wkt[d * 33 + j0];
            a0 += qv * wkr[0];
            a1 += qv * wkr[1];
            a2 += qv * wkr[2];
            a3 += qv * wkr[3];
        }
        Ms[i * 34 + j0 + 0] = a0;
        Ms[i * 34 + j0 + 1] = a1;
        Ms[i * 34 + j0 + 2] = a2;
        Ms[i * 34 + j0 + 3] = a3;
    }
    __syncthreads();

    {
        const int tx = tid & 15, ty = tid >> 4;
        const int c0 = tx * 2;
        float a0[8], a1[8];
        #pragma unroll
        for (int i = 0; i < 8; i++) { a0[i] = 0.f; a1[i] = 0.f; }
        #pragma unroll 8
        for (int c = 0; c < C_; c++) {
            float2 m2 = *(const float2*)&Ms[c * 34 + c0];
            #pragma unroll
            for (int i = 0; i < 8; i++) {
                float xv = xs[(ty * 8 + i) * 36 + c];
                a0[i] += xv * m2.x;
                a1[i] += xv * m2.y;
            }
        }
        #pragma unroll
        for (int i = 0; i < 8; i++) {
            ysb[(ty * 8 + i) * 36 + c0 + 0] = a0[i];
            ysb[(ty * 8 + i) * 36 + c0 + 1] = a1[i];
        }
    }
    __syncthreads();

    {
        float4* yg = (float4*)(g_y + row0 * C_);
        #pragma unroll
        for (int it = 0; it < 4; it++) {
            int lin = tid + it * 256;
            int r = lin >> 3, c4 = lin & 7;
            yg[lin] = *(const float4*)&ysb[r * 36 + c4 * 4];
        }
    }
}

// ---------------------------------------------------------------------------
// Kernel 1: split-K attention partials.  S-pass = 3xTF32 mma.sync
// (A = y pre-split hi/lo exact; B = x split in registers; fp32-grade accuracy).
// Z-pass / exp / double-buffer / prefetch identical to the proven R16 kernel.
// One CTA = (b, qt, chunk): k-tiles [4*chunk, min(2qt+2, 4*chunk+4)).
// ---------------------------------------------------------------------------
__global__ __launch_bounds__(256, 2) void attn_kernel(const float* __restrict__ x)
{
    const int b     = blockIdx.y;
    const int qt    = (NQT128 - 1) - (blockIdx.x >> 4);  // heaviest first
    const int chunk = blockIdx.x & 15;
    const int k0    = chunk * CHUNKP;
    const int k1e   = 2 * qt + 2;
    if (k0 >= k1e) return;
    const int k1    = (k1e < k0 + CHUNKP) ? k1e : (k0 + CHUNKP);

    extern __shared__ float smf[];
    float* ysh = smf + YSH_OFF;
    float* ysl = smf + YSL_OFF;
    float* xT0 = smf + XT_OFF;
    float* xN0 = smf + XN_OFF;
    float* Ps  = smf + PS_OFF;

    const int tid  = threadIdx.x;
    const int w    = tid >> 5;        // warp 0..7: q rows [w*16, w*16+16)
    const int lane = tid & 31;
    const int g    = lane >> 2;       // fragment row group
    const int t    = lane & 3;        // fragment col group
    const int r0   = w * 16 + g;      // this thread's q rows r0, r0+8
    const int zr   = tid >> 3;        // Z-pass rows zr + 32*i
    const int zc   = (tid & 7) * 4;   // Z-pass cols zc..zc+3

    const float* xb = x + b * T_ * C_;

    // ---- load y tile (128x32), split into tf32 hi/lo, store transposed ----
    {
        const float4* yq = (const float4*)(g_y + (b * T_ + qt * 128) * C_);
        #pragma unroll
        for (int it = 0; it < 4; it++) {
            int lin = tid + it * 256;            // 0..1023
            int r = lin >> 3, c4 = lin & 7;
            float4 v = yq[lin];
            float vv[4] = {v.x, v.y, v.z, v.w};
            #pragma unroll
            for (int j = 0; j < 4; j++) {
                int c = c4 * 4 + j;
                uint h = f2tf32(vv[j]);
                float lo = vv[j] - __uint_as_float(h);
                ysh[c * YSP + r] = __uint_as_float(h);
                ysl[c * YSP + r] = __uint_as_float(f2tf32(lo));
            }
        }
    }

    // ---- preload k-tile k0 into buffer 0 (natural + transposed) ----
    {
        const float4* xg = (const float4*)(xb + k0 * 64 * C_);
        float4 p0 = xg[tid], p1 = xg[tid + 256];
        int r = tid >> 3, c4 = tid & 7;
        *(float4*)&xN0[r * 36 + c4 * 4] = p0;
        xT0[(c4 * 4 + 0) * XTP + r] = p0.x;
        xT0[(c4 * 4 + 1) * XTP + r] = p0.y;
        xT0[(c4 * 4 + 2) * XTP + r] = p0.z;
        xT0[(c4 * 4 + 3) * XTP + r] = p0.w;
        int r2 = r + 32;
        *(float4*)&xN0[r2 * 36 + c4 * 4] = p1;
        xT0[(c4 * 4 + 0) * XTP + r2] = p1.x;
        xT0[(c4 * 4 + 1) * XTP + r2] = p1.y;
        xT0[(c4 * 4 + 2) * XTP + r2] = p1.z;
        xT0[(c4 * 4 + 3) * XTP + r2] = p1.w;
    }

    float l0 = 0.f, l1 = 0.f;         // row sums for rows r0, r0+8
    ull z2[4][2];
    #pragma unroll
    for (int i = 0; i < 4; i++) { z2[i][0] = 0ull; z2[i][1] = 0ull; }

    for (int kt = k0; kt < k1; kt++) {
        const int buf = (kt - k0) & 1;
        const float* xTb = xT0 + buf * XT_STR;
        const float* xNb = xN0 + buf * XN_STR;

        __syncthreads();   // (A) this buf loaded; prior Z-pass done; ys ready

        // prefetch next k-tile into registers (stored after S-pass)
        float4 p0, p1;
        const bool pf = (kt + 1 < k1);
        if (pf) {
            const float4* xg = (const float4*)(xb + (kt + 1) * 64 * C_);
            p0 = xg[tid]; p1 = xg[tid + 256];
        }

        // ---- S = y * x_k^T via 3xTF32 mma: warp owns 16q x 64k ----
        float acc[8][4];
        #pragma unroll
        for (int nt = 0; nt < 8; nt++)
            #pragma unroll
            for (int j = 0; j < 4; j++) acc[nt][j] = 0.f;

        #pragma unroll
        for (int ks = 0; ks < 4; ks++) {
            const int ca = ks * 8 + t;          // A/B k-dim coords
            uint ah[4], al[4];
            ah[0] = __float_as_uint(ysh[(ca)     * YSP + r0]);
            ah[1] = __float_as_uint(ysh[(ca)     * YSP + r0 + 8]);
            ah[2] = __float_as_uint(ysh[(ca + 4) * YSP + r0]);
            ah[3] = __float_as_uint(ysh[(ca + 4) * YSP + r0 + 8]);
            al[0] = __float_as_uint(ysl[(ca)     * YSP + r0]);
            al[1] = __float_as_uint(ysl[(ca)     * YSP + r0 + 8]);
            al[2] = __float_as_uint(ysl[(ca + 4) * YSP + r0]);
            al[3] = __float_as_uint(ysl[(ca + 4) * YSP + r0 + 8]);
            #pragma unroll
            for (int nt = 0; nt < 8; nt++) {
                float braw0 = xTb[(ca)     * XTP + nt * 8 + g];
                float braw1 = xTb[(ca + 4) * XTP + nt * 8 + g];
                uint bh0 = f2tf32(braw0);
                uint bh1 = f2tf32(braw1);
                uint bl0 = f2tf32(braw0 - __uint_as_float(bh0));
                uint bl1 = f2tf32(braw1 - __uint_as_float(bh1));
                mma_tf32(acc[nt], ah, bh0, bh1);
                mma_tf32(acc[nt], al, bh0, bh1);
                mma_tf32(acc[nt], ah, bl0, bl1);
            }
        }

        // ---- causal mask on fragment coords (last two k-tiles only) ----
        if (kt >= 2 * qt) {
            const int koff = (kt - 2 * qt) * 64;
            #pragma unroll
            for (int nt = 0; nt < 8; nt++) {
                const int col = koff + nt * 8 + 2 * t;
                if (col     > r0)     acc[nt][0] = -1e30f;
                if (col + 1 > r0)     acc[nt][1] = -1e30f;
                if (col     > r0 + 8) acc[nt][2] = -1e30f;
                if (col + 1 > r0 + 8) acc[nt][3] = -1e30f;
            }
        }

        // ---- store prefetched tile into other buffer ----
        if (pf) {
            const int nb = buf ^ 1;
            float* xNn = xN0 + nb * XN_STR;
            float* xTn = xT0 + nb * XT_STR;
            int r = tid >> 3, c4 = tid & 7;
            *(float4*)&xNn[r * 36 + c4 * 4] = p0;
            xTn[(c4 * 4 + 0) * XTP + r] = p0.x;
            xTn[(c4 * 4 + 1) * XTP + r] = p0.y;
            xTn[(c4 * 4 + 2) * XTP + r] = p0.z;
            xTn[(c4 * 4 + 3) * XTP + r] = p0.w;
            int r2 = r + 32;
            *(float4*)&xNn[r2 * 36 + c4 * 4] = p1;
            xTn[(c4 * 4 + 0) * XTP + r2] = p1.x;
            xTn[(c4 * 4 + 1) * XTP + r2] = p1.y;
            xTn[(c4 * 4 + 2) * XTP + r2] = p1.z;
            xTn[(c4 * 4 + 3) * XTP + r2] = p1.w;
        }

        // ---- p = exp(s), local row sums, store P into Ps ----
        #pragma unroll
        for (int nt = 0; nt < 8; nt++) {
            float e0 = __expf(acc[nt][0]);
            float e1 = __expf(acc[nt][1]);
            float e2 = __expf(acc[nt][2]);
            float e3 = __expf(acc[nt][3]);
            l0 += e0 + e1;
            l1 += e2 + e3;
            *(float2*)&Ps[(r0)     * 68 + nt * 8 + 2 * t] = make_float2(e0, e1);
            *(float2*)&Ps[(r0 + 8) * 68 + nt * 8 + 2 * t] = make_float2(e2, e3);
        }
        __syncthreads();   // (B) Ps visible

        // ---- Z += P * x_k : rows zr+32i, cols zc..zc+3 (unchanged) ----
        #pragma unroll 4
        for (int k4 = 0; k4 < 16; k4++) {
            ulonglong2 xp[4];
            float4 pr[4];
            #pragma unroll
            for (int kk = 0; kk < 4; kk++)
                xp[kk] = *(const ulonglong2*)&xNb[(k4 * 4 + kk) * 36 + zc];
            #pragma unroll
            for (int i = 0; i < 4; i++)
                pr[i] = *(const float4*)&Ps[(zr + 32 * i) * 68 + k4 * 4];

            #pragma unroll
            for (int i = 0; i < 4; i++) {
                const float* pv = (const float*)&pr[i];
                #pragma unroll
                for (int kk = 0; kk < 4; kk++) {
                    ull pd = pack2(pv[kk], pv[kk]);
                    fma2(z2[i][0], pd, xp[kk].x);
                    fma2(z2[i][1], pd, xp[kk].y);
                }
            }
        }
    }

    // ---- write partials ----
    const int islot = (b * NQT128 + qt) * NCHUNK + chunk;

    // reduce l over the 4 lanes sharing g (t = 0..3)
    l0 += __shfl_xor_sync(0xffffffffu, l0, 1);
    l0 += __shfl_xor_sync(0xffffffffu, l0, 2);
    l1 += __shfl_xor_sync(0xffffffffu, l1, 1);
    l1 += __shfl_xor_sync(0xffffffffu, l1, 2);
    if (t == 0) {
        g_partL[islot * 128 + r0]     = l0;
        g_partL[islot * 128 + r0 + 8] = l1;
    }

    float* zp = g_partZ + islot * (128 * 32);
    #pragma unroll
    for (int i = 0; i < 4; i++) {
        float2 a = unpack2(z2[i][0]);
        float2 c = unpack2(z2[i][1]);
        *(float4*)&zp[(zr + 32 * i) * 32 + zc] = make_float4(a.x, a.y, c.x, c.y);
    }
}

// ---------------------------------------------------------------------------
// Kernel 2: reduce partials, out = (Z / l) * Wv.  512 CTAs (proven config).
// ---------------------------------------------------------------------------
__global__ __launch_bounds__(256) void reduce_kernel(
    const float* __restrict__ Wv, float* __restrict__ out)
{
    __shared__ float Zs[64][36];
    __shared__ float Wvs[32][68];
    __shared__ float lv[64];

    const int qt   = blockIdx.x >> 1;
    const int half = blockIdx.x & 1;
    const int b    = blockIdx.y;
    const int tid  = threadIdx.x;
    const int nc   = (2 * qt + 1) / CHUNKP + 1;
    const int base = (b * NQT128 + qt) * NCHUNK;
    const int row0 = half * 64;

    float4 acc[2];
    #pragma unroll
    for (int it = 0; it < 2; it++) acc[it] = make_float4(0.f, 0.f, 0.f, 0.f);
    for (int s = 0; s < nc; s++) {
        const float4* zp = (const float4*)(g_partZ + (base + s) * (128 * 32) + row0 * 32);
        #pragma unroll
        for (int it = 0; it < 2; it++) {
            float4 v = zp[tid + it * 256];
            acc[it].x += v.x; acc[it].y += v.y; acc[it].z += v.z; acc[it].w += v.w;
        }
    }
    if (tid < 64) {
        float ls = 0.f;
        for (int s = 0; s < nc; s++)
            ls += g_partL[(base + s) * 128 + row0 + tid];
        lv[tid] = 1.f / ls;
    }
    __syncthreads();

    #pragma unroll
    for (int it = 0; it < 2; it++) {
        int lin = tid + it * 256;
        int r = lin >> 3, c4 = lin & 7;
        float li = lv[r];
        *(float4*)&Zs[r][c4 * 4] = make_float4(acc[it].x * li, acc[it].y * li,
                                               acc[it].z * li, acc[it].w * li);
    }
    {
        const float4* wg = (const float4*)Wv;
        #pragma unroll
        for (int it = 0; it < 2; it++) {
            int lin = tid + it * 256;
            int r = lin >> 4, c4 = lin & 15;
            *(float4*)&Wvs[r][c4 * 4] = wg[lin];
        }
    }
    __syncthreads();

    const int tx = tid & 15, ty = tid >> 4;
    float o[4][4];
    #pragma unroll
    for (int i = 0; i < 4; i++)
        #pragma unroll
        for (int j = 0; j < 4; j++) o[i][j] = 0.f;

    #pragma unroll 4
    for (int c = 0; c < C_; c++) {
        float4 w4 = *(const float4*)&Wvs[c][tx * 4];
        #pragma unroll
        for (int i = 0; i < 4; i++) {
            float zv = Zs[ty + 16 * i][c];
            o[i][0] += zv * w4.x; o[i][1] += zv * w4.y;
            o[i][2] += zv * w4.z; o[i][3] += zv * w4.w;
        }
    }

    float* Og = out + (b * T_ + qt * 128 + row0) * D_;
    #pragma unroll
    for (int i = 0; i < 4; i++)
        *(float4*)&Og[(ty + 16 * i) * D_ + tx * 4] =
            make_float4(o[i][0], o[i][1], o[i][2], o[i][3]);
}

// ---------------------------------------------------------------------------
extern "C" void kernel_launch(void* const* d_in, const int* in_sizes, int n_in,
                              void* d_out, int out_size)
{
    const float* x  = (const float*)d_in[0];
    const float* Wk = (const float*)d_in[1];
    const float* Wq = (const float*)d_in[2];
    const float* Wv = (const float*)d_in[3];
    float* out = (float*)d_out;

    y_kernel<<<(B_ * T_) / 128, 256>>>(x, Wk, Wq);

    const int smem = SM_FLOATS * (int)sizeof(float);   // 106496 B
    cudaFuncSetAttribute(attn_kernel, cudaFuncAttributeMaxDynamicSharedMemorySize, smem);
    attn_kernel<<<dim3(NQT128 * NCHUNK, B_), 256, smem>>>(x);

    reduce_kernel<<<dim3(NQT128 * 2, B_), 256>>>(Wv, out);
}